// round 11
// baseline (speedup 1.0000x reference)
#include <cuda_runtime.h>

// PatchShuffle: RATIO=0.75, NUM_ROWS=16, NUM_COLS=64, T=1024, B=64, C=768, STRIPE_W=48
// Output layout (flat fp32):
//   visible [12,582,912] | fwd [65,536] | bwd [65,536] | stripe_bounds [128]
//
// R6 structure (warp-per-row, 6 front-batched LDG.128, folded index work),
// with write-through stores: skip the L2 allocate->evict round trip on the
// mandatory 50.6 MB output stream; reads keep default policy (L2-resident).

#define NCOLS    64
#define BATCH    64
#define SW       48
#define NVIS     16
#define ROW_F4   192           // float4 per (t,b) row
#define VIS_ELEMS 12582912LL
#define NBLOCKS  2048u         // 16384 rows / 8 warps per block

__device__ __forceinline__ int perm_of(int j, int s) {
    return (j < NVIS) ? ((j < s) ? j : j + SW) : (s + (j - NVIS));
}

__global__ void __launch_bounds__(256)
patch_shuffle_fused(const float4* __restrict__ patches,
                    const int*    __restrict__ start_cols,
                    float*        __restrict__ out) {
    const unsigned tid = threadIdx.x;
    const unsigned blk = blockIdx.x;

    // ---- index outputs folded into gather blocks: 64 elems per block ----
    if (tid < 64) {
        unsigned k = blk * 64 + tid;           // covers [0, 131072) exactly
        if (k < 65536) {
            // fwd[t, b]
            int b = k & 63;
            int t = k >> 6;
            int j = t & 63, r = t >> 6;
            int s = __ldg(&start_cols[b]);
            __stwt(&out[VIS_ELEMS + k], (float)(r * NCOLS + perm_of(j, s)));
        } else {
            // bwd[p, b] (closed-form inverse)
            unsigned m = k - 65536;
            int b = m & 63;
            int p = m >> 6;
            int c = p & 63, r = p >> 6;
            int s = __ldg(&start_cols[b]);
            int inv = (c < s) ? c : ((c < s + SW) ? (NVIS + c - s) : (c - SW));
            __stwt(&out[VIS_ELEMS + 65536 + m], (float)(r * NCOLS + inv));
        }
    } else if (blk == 0 && tid < 192) {
        // stripe_bounds: 128 elems, row 0 = start, row 1 = start + SW
        unsigned m = tid - 64;
        int b = m & 63;
        int s = __ldg(&start_cols[b]);
        __stwt(&out[VIS_ELEMS + 131072 + m], (float)((m < 64) ? s : s + SW));
    }

    // ---- gather: one warp per output row; 6 front-batched LDG.128 ----
    unsigned warp = blk * 8 + (tid >> 5);
    int lane = tid & 31;
    int b = warp & 63;
    int t = warp >> 6;                         // t in [0,256)
    int j = t & 63;
    int r = t >> 6;
    int s = __ldg(&start_cols[b]);
    int src_t = r * NCOLS + perm_of(j, s);

    const float4* src = patches + ((long)src_t * BATCH + b) * ROW_F4 + lane;
    float4*       dst = (float4*)out + (long)warp * ROW_F4 + lane;

    float4 v0 = src[0];
    float4 v1 = src[32];
    float4 v2 = src[64];
    float4 v3 = src[96];
    float4 v4 = src[128];
    float4 v5 = src[160];
    // write-through stores: output stream bypasses L2 residency entirely
    __stwt(&dst[0],   v0);
    __stwt(&dst[32],  v1);
    __stwt(&dst[64],  v2);
    __stwt(&dst[96],  v3);
    __stwt(&dst[128], v4);
    __stwt(&dst[160], v5);
}

extern "C" void kernel_launch(void* const* d_in, const int* in_sizes, int n_in,
                              void* d_out, int out_size) {
    const float4* patches    = (const float4*)d_in[0];
    const int*    start_cols = (const int*)d_in[1];
    float*        out        = (float*)d_out;

    patch_shuffle_fused<<<NBLOCKS, 256>>>(patches, start_cols, out);
}

// round 12
// speedup vs baseline: 1.0569x; 1.0569x over previous
#include <cuda_runtime.h>

// PatchShuffle: RATIO=0.75, NUM_ROWS=16, NUM_COLS=64, T=1024, B=64, C=768, STRIPE_W=48
// Output layout (flat fp32):
//   visible [12,582,912] | fwd [65,536] | bwd [65,536] | stripe_bounds [128]
//
// FINAL (R10 configuration, measured floor for this pattern on sm_103a):
//  - single launch; index outputs folded into the gather blocks
//  - one warp per output row; 6 front-batched LDG.128 (true MLP=6 at 32 regs)
//  - default-policy reads: the 50 MB input stays L2-resident across graph replays
//  - __stcs evict-first stores: write-combined streaming drain, no input eviction
// Floor = mandatory 50.6 MB output write stream to DRAM (~3.95 TB/s drain).

#define NCOLS    64
#define BATCH    64
#define SW       48
#define NVIS     16
#define ROW_F4   192           // float4 per (t,b) row
#define VIS_ELEMS 12582912LL
#define NBLOCKS  2048u         // 16384 rows / 8 warps per block

__device__ __forceinline__ int perm_of(int j, int s) {
    return (j < NVIS) ? ((j < s) ? j : j + SW) : (s + (j - NVIS));
}

__global__ void __launch_bounds__(256)
patch_shuffle_fused(const float4* __restrict__ patches,
                    const int*    __restrict__ start_cols,
                    float*        __restrict__ out) {
    const unsigned tid = threadIdx.x;
    const unsigned blk = blockIdx.x;

    // ---- index outputs folded into gather blocks: 64 elems per block ----
    if (tid < 64) {
        unsigned k = blk * 64 + tid;           // covers [0, 131072) exactly
        if (k < 65536) {
            // fwd[t, b]
            int b = k & 63;
            int t = k >> 6;
            int j = t & 63, r = t >> 6;
            int s = __ldg(&start_cols[b]);
            __stcs(&out[VIS_ELEMS + k], (float)(r * NCOLS + perm_of(j, s)));
        } else {
            // bwd[p, b] (closed-form inverse)
            unsigned m = k - 65536;
            int b = m & 63;
            int p = m >> 6;
            int c = p & 63, r = p >> 6;
            int s = __ldg(&start_cols[b]);
            int inv = (c < s) ? c : ((c < s + SW) ? (NVIS + c - s) : (c - SW));
            __stcs(&out[VIS_ELEMS + 65536 + m], (float)(r * NCOLS + inv));
        }
    } else if (blk == 0 && tid < 192) {
        // stripe_bounds: 128 elems, row 0 = start, row 1 = start + SW
        unsigned m = tid - 64;
        int b = m & 63;
        int s = __ldg(&start_cols[b]);
        __stcs(&out[VIS_ELEMS + 131072 + m], (float)((m < 64) ? s : s + SW));
    }

    // ---- gather: one warp per output row; 6 front-batched LDG.128 ----
    unsigned warp = blk * 8 + (tid >> 5);
    int lane = tid & 31;
    int b = warp & 63;
    int t = warp >> 6;                         // t in [0,256)
    int j = t & 63;
    int r = t >> 6;
    int s = __ldg(&start_cols[b]);
    int src_t = r * NCOLS + perm_of(j, s);

    const float4* src = patches + ((long)src_t * BATCH + b) * ROW_F4 + lane;
    float4*       dst = (float4*)out + (long)warp * ROW_F4 + lane;

    float4 v0 = src[0];
    float4 v1 = src[32];
    float4 v2 = src[64];
    float4 v3 = src[96];
    float4 v4 = src[128];
    float4 v5 = src[160];
    // streaming stores: evict-first so the input stays L2-resident across replays
    __stcs(&dst[0],   v0);
    __stcs(&dst[32],  v1);
    __stcs(&dst[64],  v2);
    __stcs(&dst[96],  v3);
    __stcs(&dst[128], v4);
    __stcs(&dst[160], v5);
}

extern "C" void kernel_launch(void* const* d_in, const int* in_sizes, int n_in,
                              void* d_out, int out_size) {
    const float4* patches    = (const float4*)d_in[0];
    const int*    start_cols = (const int*)d_in[1];
    float*        out        = (float*)d_out;

    patch_shuffle_fused<<<NBLOCKS, 256>>>(patches, start_cols, out);
}

// round 13
// speedup vs baseline: 1.1400x; 1.0786x over previous
#include <cuda_runtime.h>

// PatchShuffle: RATIO=0.75, NUM_ROWS=16, NUM_COLS=64, T=1024, B=64, C=768, STRIPE_W=48
// Output layout (flat fp32):
//   visible [12,582,912] | fwd [65,536] | bwd [65,536] | stripe_bounds [128]
//
// Single-wave persistent variant: 1184 blocks (148 SM x 8 CTAs) = exactly one
// wave at this occupancy. Each warp handles output row gw and, for the first
// 6912 warps, also row gw + 9472 — no second wave, no partial-wave tail.
// All proven elements kept: 6 front-batched LDG.128 per row, __stcs streaming
// stores, index outputs folded into the same launch.

#define NCOLS    64
#define BATCH    64
#define SW       48
#define NVIS     16
#define ROW_F4   192            // float4 per (t,b) row
#define VIS_ELEMS 12582912LL
#define NBLOCKS  1184u          // 148 SMs * 8 CTAs -> one wave
#define NWARPS   9472u          // NBLOCKS * 8
#define NROWS_OUT 16384u

__device__ __forceinline__ int perm_of(int j, int s) {
    return (j < NVIS) ? ((j < s) ? j : j + SW) : (s + (j - NVIS));
}

__device__ __forceinline__ void copy_row(const float4* __restrict__ patches,
                                         const int*    __restrict__ start_cols,
                                         float4*       __restrict__ outv,
                                         unsigned w, int lane) {
    int b = w & 63;
    int t = w >> 6;                     // t in [0,256)
    int j = t & 63;
    int r = t >> 6;
    int s = __ldg(&start_cols[b]);
    int src_t = r * NCOLS + perm_of(j, s);

    const float4* src = patches + ((long)src_t * BATCH + b) * ROW_F4 + lane;
    float4*       dst = outv + (long)w * ROW_F4 + lane;

    float4 v0 = src[0];
    float4 v1 = src[32];
    float4 v2 = src[64];
    float4 v3 = src[96];
    float4 v4 = src[128];
    float4 v5 = src[160];
    __stcs(&dst[0],   v0);
    __stcs(&dst[32],  v1);
    __stcs(&dst[64],  v2);
    __stcs(&dst[96],  v3);
    __stcs(&dst[128], v4);
    __stcs(&dst[160], v5);
}

__global__ void __launch_bounds__(256)
patch_shuffle_fused(const float4* __restrict__ patches,
                    const int*    __restrict__ start_cols,
                    float*        __restrict__ out) {
    const unsigned tid = threadIdx.x;
    const unsigned blk = blockIdx.x;

    // ---- index outputs: 128 elems per block for the first 1024 blocks ----
    if (tid < 128) {
        unsigned k = blk * 128 + tid;
        if (k < 65536) {
            // fwd[t, b]
            int b = k & 63;
            int t = k >> 6;
            int j = t & 63, r = t >> 6;
            int s = __ldg(&start_cols[b]);
            __stcs(&out[VIS_ELEMS + k], (float)(r * NCOLS + perm_of(j, s)));
        } else if (k < 131072) {
            // bwd[p, b] (closed-form inverse)
            unsigned m = k - 65536;
            int b = m & 63;
            int p = m >> 6;
            int c = p & 63, r = p >> 6;
            int s = __ldg(&start_cols[b]);
            int inv = (c < s) ? c : ((c < s + SW) ? (NVIS + c - s) : (c - SW));
            __stcs(&out[VIS_ELEMS + 65536 + m], (float)(r * NCOLS + inv));
        }
    } else if (blk == 0 && tid < 256) {
        // stripe_bounds: 128 elems, row 0 = start, row 1 = start + SW
        unsigned m = tid - 128;
        int b = m & 63;
        int s = __ldg(&start_cols[b]);
        __stcs(&out[VIS_ELEMS + 131072 + m], (float)((m < 64) ? s : s + SW));
    }

    // ---- gather: persistent single wave, 1-2 rows per warp ----
    unsigned gw = blk * 8 + (tid >> 5);        // [0, 9472)
    int lane = tid & 31;

    copy_row(patches, start_cols, (float4*)out, gw, lane);
    unsigned w2 = gw + NWARPS;
    if (w2 < NROWS_OUT)
        copy_row(patches, start_cols, (float4*)out, w2, lane);
}

extern "C" void kernel_launch(void* const* d_in, const int* in_sizes, int n_in,
                              void* d_out, int out_size) {
    const float4* patches    = (const float4*)d_in[0];
    const int*    start_cols = (const int*)d_in[1];
    float*        out        = (float*)d_out;

    patch_shuffle_fused<<<NBLOCKS, 256>>>(patches, start_cols, out);
}

// round 14
// speedup vs baseline: 1.1600x; 1.0175x over previous
#include <cuda_runtime.h>

// PatchShuffle: RATIO=0.75, NUM_ROWS=16, NUM_COLS=64, T=1024, B=64, C=768, STRIPE_W=48
// Output layout (flat fp32):
//   visible [12,582,912] | fwd [65,536] | bwd [65,536] | stripe_bounds [128]
//
// FINAL (best-measured configuration, 12.77 us):
//  - single launch; index outputs folded into the gather blocks
//  - one warp per output row; 6 front-batched LDG.128 (true MLP=6 at 32 regs)
//  - default-policy reads: the 50 MB input stays L2-resident across graph replays
//  - __stcs evict-first stores: write-combined streaming drain, no input eviction
// Floor = mandatory 50.6 MB output write stream to DRAM (~3.9 TB/s drain).
// Verified-equivalent variants (within bench noise): 1184-block single wave,
// 2-rows-per-warp MLP-12. Regressions: __stwt, evict_last reads, cp.async.bulk.

#define NCOLS    64
#define BATCH    64
#define SW       48
#define NVIS     16
#define ROW_F4   192           // float4 per (t,b) row
#define VIS_ELEMS 12582912LL
#define NBLOCKS  2048u         // 16384 rows / 8 warps per block

__device__ __forceinline__ int perm_of(int j, int s) {
    return (j < NVIS) ? ((j < s) ? j : j + SW) : (s + (j - NVIS));
}

__global__ void __launch_bounds__(256)
patch_shuffle_fused(const float4* __restrict__ patches,
                    const int*    __restrict__ start_cols,
                    float*        __restrict__ out) {
    const unsigned tid = threadIdx.x;
    const unsigned blk = blockIdx.x;

    // ---- index outputs folded into gather blocks: 64 elems per block ----
    if (tid < 64) {
        unsigned k = blk * 64 + tid;           // covers [0, 131072) exactly
        if (k < 65536) {
            // fwd[t, b]
            int b = k & 63;
            int t = k >> 6;
            int j = t & 63, r = t >> 6;
            int s = __ldg(&start_cols[b]);
            __stcs(&out[VIS_ELEMS + k], (float)(r * NCOLS + perm_of(j, s)));
        } else {
            // bwd[p, b] (closed-form inverse)
            unsigned m = k - 65536;
            int b = m & 63;
            int p = m >> 6;
            int c = p & 63, r = p >> 6;
            int s = __ldg(&start_cols[b]);
            int inv = (c < s) ? c : ((c < s + SW) ? (NVIS + c - s) : (c - SW));
            __stcs(&out[VIS_ELEMS + 65536 + m], (float)(r * NCOLS + inv));
        }
    } else if (blk == 0 && tid < 192) {
        // stripe_bounds: 128 elems, row 0 = start, row 1 = start + SW
        unsigned m = tid - 64;
        int b = m & 63;
        int s = __ldg(&start_cols[b]);
        __stcs(&out[VIS_ELEMS + 131072 + m], (float)((m < 64) ? s : s + SW));
    }

    // ---- gather: one warp per output row; 6 front-batched LDG.128 ----
    unsigned warp = blk * 8 + (tid >> 5);
    int lane = tid & 31;
    int b = warp & 63;
    int t = warp >> 6;                         // t in [0,256)
    int j = t & 63;
    int r = t >> 6;
    int s = __ldg(&start_cols[b]);
    int src_t = r * NCOLS + perm_of(j, s);

    const float4* src = patches + ((long)src_t * BATCH + b) * ROW_F4 + lane;
    float4*       dst = (float4*)out + (long)warp * ROW_F4 + lane;

    float4 v0 = src[0];
    float4 v1 = src[32];
    float4 v2 = src[64];
    float4 v3 = src[96];
    float4 v4 = src[128];
    float4 v5 = src[160];
    // streaming stores: evict-first so the input stays L2-resident across replays
    __stcs(&dst[0],   v0);
    __stcs(&dst[32],  v1);
    __stcs(&dst[64],  v2);
    __stcs(&dst[96],  v3);
    __stcs(&dst[128], v4);
    __stcs(&dst[160], v5);
}

extern "C" void kernel_launch(void* const* d_in, const int* in_sizes, int n_in,
                              void* d_out, int out_size) {
    const float4* patches    = (const float4*)d_in[0];
    const int*    start_cols = (const int*)d_in[1];
    float*        out        = (float*)d_out;

    patch_shuffle_fused<<<NBLOCKS, 256>>>(patches, start_cols, out);
}